// round 1
// baseline (speedup 1.0000x reference)
#include <cuda_runtime.h>
#include <math.h>

#define M 4096
#define CN 64
#define BNEPS 1e-5

// ---------------- scratch (device globals; no allocs allowed) ----------------
__device__ float g_table[5*16*64*16];                 // 320 KB
__device__ float g_bn0s1[CN], g_bn0s2[CN];
__device__ float g_bn1s[CN],  g_bn1q[CN];
__device__ float g_bn2s[CN],  g_bn2q[CN];
__device__ float g_scale0[CN], g_shift0[CN], g_u0[CN];
__device__ float g_base_r[CN*32];                     // u0*W4 + b_rank
__device__ float g_rc3[CN*32];
__device__ float g_scale1[CN], g_shift1[CN];
__device__ float g_rc4[CN*16];
__device__ float g_scale2[CN], g_shift2[CN];
__device__ float g_outconst[16];
__device__ float g_r3[(size_t)CN*4*32*M];             // 128 MB, layout [c][h][o][m]
__device__ float g_r4[(size_t)CN*4*16*M];             // 64 MB,  layout [c][h][o][m]

// ---------------- k_init: zero accumulators (graph is replayed!) -------------
__global__ void kinit() {
    int t = threadIdx.x;
    if (t < CN) {
        g_bn0s1[t]=0.f; g_bn0s2[t]=0.f;
        g_bn1s[t]=0.f;  g_bn1q[t]=0.f;
        g_bn2s[t]=0.f;  g_bn2q[t]=0.f;
    }
}

// ---------------- k_table: sparse-conv lookup table ---------------------------
// T[i][combo][c][h*4+w] = conv_w[c,i,r-h,s-w] if h<=r && w<=s else 0
__global__ void ktable(const float* __restrict__ conv_w) {
    int idx = blockIdx.x*blockDim.x + threadIdx.x;   // 81920 total
    if (idx >= 5*16*64*16) return;
    int hw = idx & 15, c = (idx>>4)&63, combo = (idx>>10)&15, i = idx>>14;
    int h = hw>>2, w = hw&3, r = combo>>2, s = combo&3;
    float v = 0.f;
    if (h <= r && w <= s) v = conv_w[c*125 + i*25 + (r-h)*5 + (s-w)];
    g_table[idx] = v;
}

// a[m,c,:,:] (4x4) = sum over 5 cards of table rows
__device__ __forceinline__ void compute_a(int m, int c, const int* __restrict__ x, float* a) {
#pragma unroll
    for (int k = 0; k < 16; k++) a[k] = 0.f;
#pragma unroll
    for (int i = 0; i < 5; i++) {
        int r = x[m*10 + 2*i]     & 3;
        int s = x[m*10 + 2*i + 1] & 3;
        const float4* tp = reinterpret_cast<const float4*>(
            g_table + (i*16 + (r*4 + s))*1024 + c*16);
        float4 t0 = tp[0], t1 = tp[1], t2 = tp[2], t3 = tp[3];
        a[0]+=t0.x; a[1]+=t0.y; a[2]+=t0.z; a[3]+=t0.w;
        a[4]+=t1.x; a[5]+=t1.y; a[6]+=t1.z; a[7]+=t1.w;
        a[8]+=t2.x; a[9]+=t2.y; a[10]+=t2.z; a[11]+=t2.w;
        a[12]+=t3.x; a[13]+=t3.y; a[14]+=t3.z; a[15]+=t3.w;
    }
}

// ---------------- k1: BN0 raw sums over the varying 4x4 region ----------------
__global__ void __launch_bounds__(128) k1(const int* __restrict__ x) {
    int c  = blockIdx.y;
    int mp = blockIdx.x*128 + threadIdx.x;
    float a0[16], a1[16];
    compute_a(2*mp,   c, x, a0);
    compute_a(2*mp+1, c, x, a1);
    float s = 0.f, q = 0.f;
#pragma unroll
    for (int k = 0; k < 16; k++) {
        s += a0[k] + a1[k];
        q += a0[k]*a0[k] + a1[k]*a1[k];
    }
    for (int off = 16; off; off >>= 1) {
        s += __shfl_down_sync(0xffffffffu, s, off);
        q += __shfl_down_sync(0xffffffffu, q, off);
    }
    __shared__ float ss[4], sq[4];
    int w = threadIdx.x >> 5, l = threadIdx.x & 31;
    if (!l) { ss[w] = s; sq[w] = q; }
    __syncthreads();
    if (threadIdx.x == 0) {
        atomicAdd(&g_bn0s1[c], ss[0]+ss[1]+ss[2]+ss[3]);
        atomicAdd(&g_bn0s2[c], sq[0]+sq[1]+sq[2]+sq[3]);
    }
}

// ---------------- k2: finalize BN0, const path through w_rank/w_h1 -----------
__global__ void k2(const float* __restrict__ conv_b,
                   const float* __restrict__ bn0_g, const float* __restrict__ bn0_b,
                   const float* __restrict__ w_rank, const float* __restrict__ b_rank,
                   const float* __restrict__ w_h1,  const float* __restrict__ b_h1) {
    __shared__ float shW4[32], shWall[32];
    __shared__ float sh_rc2[64*32];
    __shared__ float cs[64], cq[64];
    int t = threadIdx.x;                              // 256
    if (t < 64) {
        double n0   = (double)M * 110.0;
        double mu_a = (double)g_bn0s1[t] / n0;
        double var  = (double)g_bn0s2[t] / n0 - mu_a*mu_a;
        double cb   = (double)conv_b[t];
        double mean = cb + mu_a;
        double sc   = (double)bn0_g[t] / sqrt(var + BNEPS);
        double sh   = (double)bn0_b[t] - mean*sc;
        g_scale0[t] = (float)sc;
        g_shift0[t] = (float)sh;
        g_u0[t]     = fmaxf((float)(cb*sc + sh), 0.f);
        cs[t] = 0.f; cq[t] = 0.f;
    }
    if (t < 32) {
        float w4 = 0.f, wall = 0.f;
        for (int w = 0; w < 10; w++) { float v = w_rank[t*10+w]; wall += v; if (w >= 4) w4 += v; }
        shW4[t] = w4; shWall[t] = wall;
    }
    __syncthreads();
    for (int idx = t; idx < 2048; idx += 256) {
        int c = idx >> 5, o = idx & 31;
        g_base_r[idx] = g_u0[c]*shW4[o] + b_rank[o];
        sh_rc2[idx]   = fmaxf(g_u0[c]*shWall[o] + b_rank[o], 0.f);
    }
    __syncthreads();
    for (int idx = t; idx < 2048; idx += 256) {
        int c = idx >> 5, o = idx & 31;
        float acc = b_h1[o];
        for (int i = 0; i < 32; i++) acc += sh_rc2[c*32+i] * w_h1[o*32+i];
        g_rc3[idx] = acc;
        atomicAdd(&cs[c], acc);
        atomicAdd(&cq[c], acc*acc);
    }
    __syncthreads();
    if (t < 64) {                                     // constant rows: M * 7 copies each
        float k = (float)(M*7);
        g_bn1s[t] += k*cs[t];
        g_bn1q[t] += k*cq[t];
    }
}

// ---------------- k3: fused bn0+relu -> w_rank+relu -> w_h1, BN1 sums --------
__global__ void __launch_bounds__(128) k3(const int* __restrict__ x,
                                          const float* __restrict__ conv_b,
                                          const float* __restrict__ w_rank,
                                          const float* __restrict__ w_h1,
                                          const float* __restrict__ b_h1) {
    __shared__ float sw4[32*4], swh1[32*32], sb1[32], sbase[32];
    __shared__ float red_s, red_q;
    int c = blockIdx.y, t = threadIdx.x;
    for (int idx = t; idx < 1024; idx += 128) swh1[idx] = w_h1[idx];
    if (t < 32) {
        sb1[t]   = b_h1[t];
        sbase[t] = g_base_r[c*32 + t];
#pragma unroll
        for (int w = 0; w < 4; w++) sw4[t*4+w] = w_rank[t*10+w];
    }
    if (t == 0) { red_s = 0.f; red_q = 0.f; }
    __syncthreads();

    int mp = blockIdx.x*128 + t;
    float sc0 = g_scale0[c];
    float pc0 = conv_b[c]*sc0 + g_shift0[c];
    float a0[16], a1[16];
    compute_a(2*mp,   c, x, a0);
    compute_a(2*mp+1, c, x, a1);
#pragma unroll
    for (int k = 0; k < 16; k++) {                    // bn0 + relu
        a0[k] = fmaxf(a0[k]*sc0 + pc0, 0.f);
        a1[k] = fmaxf(a1[k]*sc0 + pc0, 0.f);
    }
    float s = 0.f, q = 0.f;
#pragma unroll
    for (int h = 0; h < 4; h++) {
        float r20[32], r21[32];
#pragma unroll
        for (int o = 0; o < 32; o++) {                // w_rank stage (+const tail) + relu
            float acc0 = sbase[o], acc1 = sbase[o];
#pragma unroll
            for (int w = 0; w < 4; w++) {
                float wv = sw4[o*4+w];
                acc0 += a0[h*4+w]*wv;
                acc1 += a1[h*4+w]*wv;
            }
            r20[o] = fmaxf(acc0, 0.f);
            r21[o] = fmaxf(acc1, 0.f);
        }
        for (int o = 0; o < 32; o++) {                // w_h1 stage
            float acc0 = sb1[o], acc1 = acc0;
#pragma unroll
            for (int i = 0; i < 32; i++) {
                float wv = swh1[o*32+i];
                acc0 += r20[i]*wv;
                acc1 += r21[i]*wv;
            }
            s += acc0 + acc1;
            q += acc0*acc0 + acc1*acc1;
            *reinterpret_cast<float2*>(&g_r3[(size_t)((c*4+h)*32+o)*M + 2*mp]) =
                make_float2(acc0, acc1);
        }
    }
    for (int off = 16; off; off >>= 1) {
        s += __shfl_down_sync(0xffffffffu, s, off);
        q += __shfl_down_sync(0xffffffffu, q, off);
    }
    if ((t & 31) == 0) { atomicAdd(&red_s, s); atomicAdd(&red_q, q); }
    __syncthreads();
    if (t == 0) { atomicAdd(&g_bn1s[c], red_s); atomicAdd(&g_bn1q[c], red_q); }
}

// ---------------- k4: finalize BN1, const path through w_h2 -------------------
__global__ void k4(const float* __restrict__ bn1_g, const float* __restrict__ bn1_b,
                   const float* __restrict__ w_h2,  const float* __restrict__ b_h2) {
    __shared__ float rc3bn[64*32];
    __shared__ float cs[64], cq[64];
    int t = threadIdx.x;                              // 256
    if (t < 64) {
        double n1   = (double)M * 11.0 * 32.0;
        double mean = (double)g_bn1s[t] / n1;
        double var  = (double)g_bn1q[t] / n1 - mean*mean;
        double sc   = (double)bn1_g[t] / sqrt(var + BNEPS);
        double sh   = (double)bn1_b[t] - mean*sc;
        g_scale1[t] = (float)sc;
        g_shift1[t] = (float)sh;
        cs[t] = 0.f; cq[t] = 0.f;
    }
    __syncthreads();
    for (int idx = t; idx < 2048; idx += 256) {
        int c = idx >> 5;
        rc3bn[idx] = fmaxf(g_rc3[idx]*g_scale1[c] + g_shift1[c], 0.f);
    }
    __syncthreads();
    for (int idx = t; idx < 1024; idx += 256) {
        int c = idx >> 4, o = idx & 15;
        float acc = b_h2[o];
        for (int i = 0; i < 32; i++) acc += rc3bn[c*32+i] * w_h2[o*32+i];
        g_rc4[idx] = acc;
        atomicAdd(&cs[c], acc);
        atomicAdd(&cq[c], acc*acc);
    }
    __syncthreads();
    if (t < 64) {
        float k = (float)(M*7);
        g_bn2s[t] += k*cs[t];
        g_bn2q[t] += k*cq[t];
    }
}

// ---------------- k5: fused bn1+relu -> w_h2, BN2 sums ------------------------
__global__ void __launch_bounds__(128) k5(const float* __restrict__ w_h2,
                                          const float* __restrict__ b_h2) {
    __shared__ float swh2[16*32], sb2[16];
    __shared__ float red_s, red_q;
    int c = blockIdx.y, t = threadIdx.x;
    for (int idx = t; idx < 512; idx += 128) swh2[idx] = w_h2[idx];
    if (t < 16) sb2[t] = b_h2[t];
    if (t == 0) { red_s = 0.f; red_q = 0.f; }
    __syncthreads();

    int mp = blockIdx.x*128 + t;
    float sc1 = g_scale1[c], sf1 = g_shift1[c];
    float s = 0.f, q = 0.f;
    for (int h = 0; h < 4; h++) {
        float y0[32], y1[32];
#pragma unroll
        for (int i = 0; i < 32; i++) {
            float2 v = *reinterpret_cast<const float2*>(&g_r3[(size_t)((c*4+h)*32+i)*M + 2*mp]);
            y0[i] = fmaxf(v.x*sc1 + sf1, 0.f);
            y1[i] = fmaxf(v.y*sc1 + sf1, 0.f);
        }
        for (int o = 0; o < 16; o++) {
            float acc0 = sb2[o], acc1 = acc0;
#pragma unroll
            for (int i = 0; i < 32; i++) {
                float wv = swh2[o*32+i];
                acc0 += y0[i]*wv;
                acc1 += y1[i]*wv;
            }
            s += acc0 + acc1;
            q += acc0*acc0 + acc1*acc1;
            *reinterpret_cast<float2*>(&g_r4[(size_t)((c*4+h)*16+o)*M + 2*mp]) =
                make_float2(acc0, acc1);
        }
    }
    for (int off = 16; off; off >>= 1) {
        s += __shfl_down_sync(0xffffffffu, s, off);
        q += __shfl_down_sync(0xffffffffu, q, off);
    }
    if ((t & 31) == 0) { atomicAdd(&red_s, s); atomicAdd(&red_q, q); }
    __syncthreads();
    if (t == 0) { atomicAdd(&g_bn2s[c], red_s); atomicAdd(&g_bn2q[c], red_q); }
}

// ---------------- k6: finalize BN2, constant-row output contribution ----------
__global__ void k6(const float* __restrict__ bn2_g, const float* __restrict__ bn2_b,
                   const float* __restrict__ w_out, const float* __restrict__ b_out) {
    __shared__ float rc5[64*16];
    int t = threadIdx.x;                              // 288 = 9 warps
    if (t < 64) {
        double n2   = (double)M * 11.0 * 16.0;
        double mean = (double)g_bn2s[t] / n2;
        double var  = (double)g_bn2q[t] / n2 - mean*mean;
        double sc   = (double)bn2_g[t] / sqrt(var + BNEPS);
        double sh   = (double)bn2_b[t] - mean*sc;
        g_scale2[t] = (float)sc;
        g_shift2[t] = (float)sh;
    }
    __syncthreads();
    for (int idx = t; idx < 1024; idx += 288) {
        int c = idx >> 4;
        rc5[idx] = fmaxf(g_rc4[idx]*g_scale2[c] + g_shift2[c], 0.f);
    }
    __syncthreads();
    int j = t >> 5, lane = t & 31;
    if (j < 9) {
        float acc = 0.f;
        for (int p = lane; p < 1024; p += 32) {
            int c = p >> 4, o = p & 15;
            float ws = 0.f;
#pragma unroll
            for (int h = 4; h < 11; h++) ws += w_out[j*11264 + c*176 + h*16 + o];
            acc += rc5[p]*ws;
        }
        for (int off = 16; off; off >>= 1) acc += __shfl_down_sync(0xffffffffu, acc, off);
        if (!lane) g_outconst[j] = b_out[j] + acc;
    }
}

// ---------------- k6b: seed output with constant part -------------------------
__global__ void k6b(float* __restrict__ out) {
    int idx = blockIdx.x*256 + threadIdx.x;
    if (idx < M*9) out[idx] = g_outconst[idx % 9];
}

// ---------------- k7: varying-feature GEMM (bn2+relu fused), feature-split ----
__global__ void __launch_bounds__(256) k7(const float* __restrict__ w_out,
                                          float* __restrict__ out) {
    __shared__ float sw[9*64];
    int t = threadIdx.x;
    int warp = t >> 5, lane = t & 31;
    int mbase = blockIdx.x*512 + warp*64 + lane*2;    // gridDim.x = 8
    int c0 = blockIdx.y*2;                            // gridDim.y = 32 (2 channels each)
    float acc0[9], acc1[9];
#pragma unroll
    for (int j = 0; j < 9; j++) { acc0[j] = 0.f; acc1[j] = 0.f; }
    for (int cc = 0; cc < 2; cc++) {
        int c = c0 + cc;
        __syncthreads();
        for (int idx = t; idx < 576; idx += 256) {
            int j = idx / 64, qq = idx % 64;          // feature-within-channel (h*16+o)
            sw[idx] = w_out[j*11264 + c*176 + qq];
        }
        __syncthreads();
        float sc = g_scale2[c], sf = g_shift2[c];
        for (int qq = 0; qq < 64; qq++) {
            float2 v = *reinterpret_cast<const float2*>(&g_r4[(size_t)(c*64+qq)*M + mbase]);
            float v0 = fmaxf(v.x*sc + sf, 0.f);
            float v1 = fmaxf(v.y*sc + sf, 0.f);
#pragma unroll
            for (int j = 0; j < 9; j++) {
                float wv = sw[j*64+qq];
                acc0[j] += v0*wv;
                acc1[j] += v1*wv;
            }
        }
    }
#pragma unroll
    for (int j = 0; j < 9; j++) {
        atomicAdd(&out[(size_t)mbase*9 + j],     acc0[j]);
        atomicAdd(&out[(size_t)(mbase+1)*9 + j], acc1[j]);
    }
}

// ---------------- launch ------------------------------------------------------
extern "C" void kernel_launch(void* const* d_in, const int* in_sizes, int n_in,
                              void* d_out, int out_size) {
    const int*   x      = (const int*)  d_in[0];
    const float* conv_w = (const float*)d_in[1];
    const float* conv_b = (const float*)d_in[2];
    const float* bn0_g  = (const float*)d_in[3];
    const float* bn0_b  = (const float*)d_in[4];
    const float* w_rank = (const float*)d_in[5];
    const float* b_rank = (const float*)d_in[6];
    const float* w_h1   = (const float*)d_in[7];
    const float* b_h1   = (const float*)d_in[8];
    const float* bn1_g  = (const float*)d_in[9];
    const float* bn1_b  = (const float*)d_in[10];
    const float* w_h2   = (const float*)d_in[11];
    const float* b_h2   = (const float*)d_in[12];
    const float* bn2_g  = (const float*)d_in[13];
    const float* bn2_b  = (const float*)d_in[14];
    const float* w_out  = (const float*)d_in[15];
    const float* b_out  = (const float*)d_in[16];
    float* out = (float*)d_out;

    kinit<<<1, 64>>>();
    ktable<<<80, 1024>>>(conv_w);
    k1<<<dim3(16, 64), 128>>>(x);
    k2<<<1, 256>>>(conv_b, bn0_g, bn0_b, w_rank, b_rank, w_h1, b_h1);
    k3<<<dim3(16, 64), 128>>>(x, conv_b, w_rank, w_h1, b_h1);
    k4<<<1, 256>>>(bn1_g, bn1_b, w_h2, b_h2);
    k5<<<dim3(16, 64), 128>>>(w_h2, b_h2);
    k6<<<1, 288>>>(bn2_g, bn2_b, w_out, b_out);
    k6b<<<144, 256>>>(out);
    k7<<<dim3(8, 32), 256>>>(w_out, out);
}